// round 2
// baseline (speedup 1.0000x reference)
#include <cuda_runtime.h>
#include <math.h>

// Problem constants (buffers sized to these; runtime N/E read from in_sizes).
#define MAXN 30000
#define MAXE 300000
#define NB   64
#define HC   256

// ---------------- scratch (device globals; no allocation allowed) ----------
__device__ float    g_h0  [MAXN*128];
__device__ float    g_xl  [MAXN*HC];
__device__ float    g_xr  [MAXN*HC];
__device__ float    g_h1  [MAXN*HC];
__device__ float    g_h2  [MAXN*HC];
__device__ float    g_agg [MAXN*HC];
__device__ float    g_logit[MAXE*4];
__device__ float    g_wbuf [MAXE*4];
__device__ unsigned g_mkey [MAXN*4];
__device__ float    g_den  [MAXN*4];
__device__ float    g_a   [MAXN*HC];
__device__ unsigned g_gmkey[NB*HC];
__device__ float    g_gsum [NB*HC];
__device__ float    g_gvec [NB*HC];
__device__ float    g_y   [NB*HC];
__device__ float    g_yact[NB*HC];

// ---------------- float <-> monotone unsigned key (for atomic max) ---------
__device__ __forceinline__ unsigned fkey(float x) {
    unsigned u = __float_as_uint(x);
    return (u & 0x80000000u) ? ~u : (u | 0x80000000u);
}
__device__ __forceinline__ float funkey(unsigned k) {
    return (k & 0x80000000u) ? __uint_as_float(k ^ 0x80000000u)
                             : __uint_as_float(~k);
}
#define NEG_INF_KEY 0x007fffffu   // fkey(-inf)

// ---------------- generic tiled fp32 GEMM: C = A[M,K] @ B[K,N] + bias ------
// BM=128, BN=64, BK=16, 256 threads, 8x4 register tile.
// slope < 0: no activation; slope >= 0: leaky_relu with that negative slope.
__global__ void gemm_bias(const float* __restrict__ A, const float* __restrict__ Bw,
                          const float* __restrict__ bias, float* __restrict__ C,
                          int M, int N, int K, float slope)
{
    __shared__ __align__(16) float As[16][128];
    __shared__ __align__(16) float Bs[16][64];
    int t  = threadIdx.x;
    int tx = t & 15;        // col group (4 cols)
    int ty = t >> 4;        // row group (8 rows)
    int rowBase = blockIdx.y * 128;
    int colBase = blockIdx.x * 64;

    float acc[8][4];
#pragma unroll
    for (int i = 0; i < 8; i++)
#pragma unroll
        for (int j = 0; j < 4; j++) acc[i][j] = 0.f;

    int nk = (K + 15) / 16;
    bool kvec = ((K & 15) == 0);
    for (int kt = 0; kt < nk; kt++) {
        int k0 = kt * 16;
        if (kvec) {
#pragma unroll
            for (int r = 0; r < 2; r++) {
                int i = t + r * 256;          // 0..511
                int m = i >> 2, kq = i & 3;
                int gm = rowBase + m;
                float4 v = make_float4(0.f, 0.f, 0.f, 0.f);
                if (gm < M) v = *(const float4*)(A + (long long)gm * K + k0 + kq * 4);
                As[kq*4+0][m] = v.x; As[kq*4+1][m] = v.y;
                As[kq*4+2][m] = v.z; As[kq*4+3][m] = v.w;
            }
        } else {
#pragma unroll
            for (int r = 0; r < 8; r++) {
                int i = t + r * 256;          // 0..2047
                int m = i >> 4, kk = i & 15;
                int gm = rowBase + m, gk = k0 + kk;
                As[kk][m] = (gm < M && gk < K) ? A[(long long)gm * K + gk] : 0.f;
            }
        }
#pragma unroll
        for (int r = 0; r < 4; r++) {
            int i = t + r * 256;              // 0..1023
            int kk = i >> 6, nn = i & 63;
            int gk = k0 + kk, gn = colBase + nn;
            Bs[kk][nn] = (gk < K && gn < N) ? Bw[(long long)gk * N + gn] : 0.f;
        }
        __syncthreads();
#pragma unroll
        for (int kk = 0; kk < 16; kk++) {
            float4 b4 = *(const float4*)&Bs[kk][tx * 4];
            float4 a0 = *(const float4*)&As[kk][ty * 8];
            float4 a1 = *(const float4*)&As[kk][ty * 8 + 4];
            float av[8] = {a0.x, a0.y, a0.z, a0.w, a1.x, a1.y, a1.z, a1.w};
            float bv[4] = {b4.x, b4.y, b4.z, b4.w};
#pragma unroll
            for (int i = 0; i < 8; i++)
#pragma unroll
                for (int j = 0; j < 4; j++) acc[i][j] += av[i] * bv[j];
        }
        __syncthreads();
    }
#pragma unroll
    for (int i = 0; i < 8; i++) {
        int gm = rowBase + ty * 8 + i;
        if (gm >= M) continue;
#pragma unroll
        for (int j = 0; j < 4; j++) {
            int gn = colBase + tx * 4 + j;
            if (gn >= N) continue;
            float v = acc[i][j] + bias[gn];
            if (slope >= 0.f) v = v > 0.f ? v : v * slope;
            C[(long long)gm * N + gn] = v;
        }
    }
}

// ---------------- init unsigned keys ---------------------------------------
__global__ void init_keys(unsigned* __restrict__ k, int n) {
    int i = blockIdx.x * blockDim.x + threadIdx.x;
    if (i < n) k[i] = NEG_INF_KEY;
}

// ---------------- GAT edge logits + segment max ----------------------------
// Block: 256 threads, 32 edges. Warp w owns edges 4w..4w+3, full 256 channels.
// Lane owns channels [4*lane, 4*lane+4) and [128+4*lane, 128+4*lane+4).
#define LOGIT_SMEM ((51*256 + 32*51) * 4)
__global__ void gat_logit(const float* __restrict__ xl, const float* __restrict__ xr,
                          const float* __restrict__ ea, const int* __restrict__ ei,
                          const float* __restrict__ We, const float* __restrict__ att,
                          float* __restrict__ logit, unsigned* __restrict__ mkey, int E)
{
    extern __shared__ __align__(16) float sm[];
    float* sWe = sm;                 // [51][256]
    float* sEa = sm + 51 * 256;      // [32][51]
    __shared__ int   sSrc[32], sDst[32];
    __shared__ float sAtt[256];

    int t = threadIdx.x;
    for (int i = t; i < 51 * 256; i += 256) sWe[i] = We[i];
    sAtt[t] = att[t];
    long long e0 = (long long)blockIdx.x * 32;
    for (int i = t; i < 32 * 51; i += 256) {
        long long e = e0 + i / 51;
        sEa[i] = (e < E) ? ea[e * 51 + (i % 51)] : 0.f;
    }
    if (t < 32) {
        long long e = e0 + t;
        sSrc[t] = (e < E) ? ei[e] : 0;
        sDst[t] = (e < E) ? ei[(long long)E + e] : 0;
    }
    __syncthreads();

    int lane = t & 31, warp = t >> 5;
    int cA = lane * 4, cB = 128 + lane * 4;

    float acc[4][8];
#pragma unroll
    for (int i = 0; i < 4; i++)
#pragma unroll
        for (int j = 0; j < 8; j++) acc[i][j] = 0.f;

    const float* eaB = sEa + warp * 4 * 51;
#pragma unroll 3
    for (int k = 0; k < 51; k++) {
        float4 wA = *(const float4*)(sWe + k * 256 + cA);
        float4 wB = *(const float4*)(sWe + k * 256 + cB);
#pragma unroll
        for (int i = 0; i < 4; i++) {
            float a = eaB[i * 51 + k];
            acc[i][0] += a * wA.x; acc[i][1] += a * wA.y;
            acc[i][2] += a * wA.z; acc[i][3] += a * wA.w;
            acc[i][4] += a * wB.x; acc[i][5] += a * wB.y;
            acc[i][6] += a * wB.z; acc[i][7] += a * wB.w;
        }
    }
    float atA[4] = {sAtt[cA], sAtt[cA+1], sAtt[cA+2], sAtt[cA+3]};
    float atB[4] = {sAtt[cB], sAtt[cB+1], sAtt[cB+2], sAtt[cB+3]};
    int hA = lane >> 4, hB = 2 + hA;

#pragma unroll
    for (int i = 0; i < 4; i++) {
        long long e = e0 + warp * 4 + i;
        if (e >= E) break;   // uniform per warp
        int s = sSrc[warp * 4 + i], d = sDst[warp * 4 + i];
        float4 xlA = *(const float4*)(xl + (long long)s * 256 + cA);
        float4 xlB = *(const float4*)(xl + (long long)s * 256 + cB);
        float4 xrA = *(const float4*)(xr + (long long)d * 256 + cA);
        float4 xrB = *(const float4*)(xr + (long long)d * 256 + cB);
        float zA[4] = {acc[i][0] + xlA.x + xrA.x, acc[i][1] + xlA.y + xrA.y,
                       acc[i][2] + xlA.z + xrA.z, acc[i][3] + xlA.w + xrA.w};
        float zB[4] = {acc[i][4] + xlB.x + xrB.x, acc[i][5] + xlB.y + xrB.y,
                       acc[i][6] + xlB.z + xrB.z, acc[i][7] + xlB.w + xrB.w};
        float pA = 0.f, pB = 0.f;
#pragma unroll
        for (int j = 0; j < 4; j++) {
            float za = zA[j] > 0.f ? zA[j] : 0.2f * zA[j];
            float zb = zB[j] > 0.f ? zB[j] : 0.2f * zB[j];
            pA += atA[j] * za;
            pB += atB[j] * zb;
        }
#pragma unroll
        for (int off = 8; off >= 1; off >>= 1) {
            pA += __shfl_xor_sync(0xffffffffu, pA, off);
            pB += __shfl_xor_sync(0xffffffffu, pB, off);
        }
        if ((lane & 15) == 0) {
            logit[e * 4 + hA] = pA;
            logit[e * 4 + hB] = pB;
            atomicMax(mkey + (long long)d * 4 + hA, fkey(pA));
            atomicMax(mkey + (long long)d * 4 + hB, fkey(pB));
        }
    }
}

// ---------------- softmax numerator + denominator --------------------------
__global__ void gat_softmax_den(const float* __restrict__ logit,
                                const int* __restrict__ ei,
                                const unsigned* __restrict__ mkey,
                                float* __restrict__ w, float* __restrict__ den, int E)
{
    int e = blockIdx.x * blockDim.x + threadIdx.x;
    if (e >= E) return;
    int d = ei[(long long)E + e];
    float4 lg = *(const float4*)(logit + (long long)e * 4);
    float m0 = funkey(mkey[d * 4 + 0]);
    float m1 = funkey(mkey[d * 4 + 1]);
    float m2 = funkey(mkey[d * 4 + 2]);
    float m3 = funkey(mkey[d * 4 + 3]);
    float w0 = expf(lg.x - m0), w1 = expf(lg.y - m1);
    float w2 = expf(lg.z - m2), w3 = expf(lg.w - m3);
    *(float4*)(w + (long long)e * 4) = make_float4(w0, w1, w2, w3);
    atomicAdd(&den[d * 4 + 0], w0);
    atomicAdd(&den[d * 4 + 1], w1);
    atomicAdd(&den[d * 4 + 2], w2);
    atomicAdd(&den[d * 4 + 3], w3);
}

// ---------------- weighted aggregation (warp per edge) ---------------------
__global__ void gat_aggregate(const float* __restrict__ xl,
                              const int* __restrict__ ei,
                              const float* __restrict__ w, const float* __restrict__ den,
                              float* __restrict__ agg, int E)
{
    int gw = (blockIdx.x * blockDim.x + threadIdx.x) >> 5;
    int lane = threadIdx.x & 31;
    if (gw >= E) return;
    long long e = gw;
    int s = ei[e], d = ei[(long long)E + e];
    int hA = lane >> 4, hB = 2 + hA;
    float aA = w[e * 4 + hA] / (den[(long long)d * 4 + hA] + 1e-16f);
    float aB = w[e * 4 + hB] / (den[(long long)d * 4 + hB] + 1e-16f);
    int cA = lane * 4, cB = 128 + lane * 4;
    float4 xA = *(const float4*)(xl + (long long)s * 256 + cA);
    float4 xB = *(const float4*)(xl + (long long)s * 256 + cB);
    float* dp = agg + (long long)d * 256;
    atomicAdd(dp + cA + 0, xA.x * aA);
    atomicAdd(dp + cA + 1, xA.y * aA);
    atomicAdd(dp + cA + 2, xA.z * aA);
    atomicAdd(dp + cA + 3, xA.w * aA);
    atomicAdd(dp + cB + 0, xB.x * aB);
    atomicAdd(dp + cB + 1, xB.y * aB);
    atomicAdd(dp + cB + 2, xB.z * aB);
    atomicAdd(dp + cB + 3, xB.w * aB);
}

// ---------------- bias add -------------------------------------------------
__global__ void add_bias(const float* __restrict__ acc, const float* __restrict__ bias,
                         float* __restrict__ out, int total)
{
    int i = blockIdx.x * blockDim.x + threadIdx.x;
    if (i < total) out[i] = acc[i] + bias[i & 255];
}

// ---------------- pooling --------------------------------------------------
__global__ void pool_max(const float* __restrict__ a, const int* __restrict__ batch,
                         unsigned* __restrict__ keys, int total)
{
    int i = blockIdx.x * blockDim.x + threadIdx.x;
    if (i >= total) return;
    int b = batch[i >> 8];
    atomicMax(&keys[b * 256 + (i & 255)], fkey(a[i]));
}
__global__ void pool_expsum(float* __restrict__ a, const int* __restrict__ batch,
                            const unsigned* __restrict__ keys, float* __restrict__ gsum,
                            int total)
{
    int i = blockIdx.x * blockDim.x + threadIdx.x;
    if (i >= total) return;
    int b = batch[i >> 8];
    int c = i & 255;
    float wv = expf(a[i] - funkey(keys[b * 256 + c]));
    a[i] = wv;
    atomicAdd(&gsum[b * 256 + c], wv);
}
__global__ void pool_weighted(const float* __restrict__ h, const float* __restrict__ a,
                              const int* __restrict__ batch,
                              const float* __restrict__ gsum, float* __restrict__ g,
                              int total)
{
    int i = blockIdx.x * blockDim.x + threadIdx.x;
    if (i >= total) return;
    int b = batch[i >> 8];
    int c = i & 255;
    float attw = a[i] / (gsum[b * 256 + c] + 1e-16f);
    atomicAdd(&g[b * 256 + c], h[i] * attw);
}

// ---------------- batchnorm (train stats) + relu ---------------------------
__global__ void bn_relu(const float* __restrict__ y, const float* __restrict__ gamma,
                        const float* __restrict__ beta, float* __restrict__ yact)
{
    int c = threadIdx.x;   // 256 threads, 1 block
    float s = 0.f, s2 = 0.f;
    for (int m = 0; m < NB; m++) {
        float v = y[m * 256 + c];
        s += v; s2 += v * v;
    }
    float mu = s * (1.f / NB);
    float var = s2 * (1.f / NB) - mu * mu;
    float inv = rsqrtf(var + 1e-5f);
    float ga = gamma[c], be = beta[c];
    for (int m = 0; m < NB; m++) {
        float v = (y[m * 256 + c] - mu) * inv * ga + be;
        yact[m * 256 + c] = v > 0.f ? v : 0.f;
    }
}

// ---------------- launcher --------------------------------------------------
extern "C" void kernel_launch(void* const* d_in, const int* in_sizes, int n_in,
                              void* d_out, int out_size)
{
    const float* x     = (const float*)d_in[0];
    const int*   ei    = (const int*)d_in[1];
    const float* ea    = (const float*)d_in[2];
    const int*   batch = (const int*)d_in[3];
    const float* W0   = (const float*)d_in[4];  const float* b0   = (const float*)d_in[5];
    const float* Wl1  = (const float*)d_in[6];  const float* bl1  = (const float*)d_in[7];
    const float* Wr1  = (const float*)d_in[8];  const float* br1  = (const float*)d_in[9];
    const float* We1  = (const float*)d_in[10]; const float* att1 = (const float*)d_in[11];
    const float* bias1= (const float*)d_in[12];
    const float* Wl2  = (const float*)d_in[13]; const float* bl2  = (const float*)d_in[14];
    const float* Wr2  = (const float*)d_in[15]; const float* br2  = (const float*)d_in[16];
    const float* We2  = (const float*)d_in[17]; const float* att2 = (const float*)d_in[18];
    const float* bias2= (const float*)d_in[19];
    const float* Wp   = (const float*)d_in[20]; const float* bp   = (const float*)d_in[21];
    const float* Wo1  = (const float*)d_in[22]; const float* bo1  = (const float*)d_in[23];
    const float* gamma= (const float*)d_in[24]; const float* beta = (const float*)d_in[25];
    const float* Wo2  = (const float*)d_in[26]; const float* bo2  = (const float*)d_in[27];
    float* out = (float*)d_out;

    const int N = in_sizes[0] / 13;
    const int E = in_sizes[2] / 51;
    const int NOUT = in_sizes[26] / 256;   // 2001

    float *h0, *xl, *xr, *h1, *h2, *agg, *logit, *wbuf, *den, *a, *gsum, *gvec, *y, *yact;
    unsigned *mkey, *gmkey;
    cudaGetSymbolAddress((void**)&h0,   g_h0);
    cudaGetSymbolAddress((void**)&xl,   g_xl);
    cudaGetSymbolAddress((void**)&xr,   g_xr);
    cudaGetSymbolAddress((void**)&h1,   g_h1);
    cudaGetSymbolAddress((void**)&h2,   g_h2);
    cudaGetSymbolAddress((void**)&agg,  g_agg);
    cudaGetSymbolAddress((void**)&logit,g_logit);
    cudaGetSymbolAddress((void**)&wbuf, g_wbuf);
    cudaGetSymbolAddress((void**)&mkey, g_mkey);
    cudaGetSymbolAddress((void**)&den,  g_den);
    cudaGetSymbolAddress((void**)&a,    g_a);
    cudaGetSymbolAddress((void**)&gmkey,g_gmkey);
    cudaGetSymbolAddress((void**)&gsum, g_gsum);
    cudaGetSymbolAddress((void**)&gvec, g_gvec);
    cudaGetSymbolAddress((void**)&y,    g_y);
    cudaGetSymbolAddress((void**)&yact, g_yact);

    cudaFuncSetAttribute(gat_logit, cudaFuncAttributeMaxDynamicSharedMemorySize, LOGIT_SMEM);

    auto gemm = [&](const float* A, const float* Bw, const float* bias, float* C,
                    int M, int Nc, int K, float slope) {
        dim3 grid((Nc + 63) / 64, (M + 127) / 128);
        gemm_bias<<<grid, 256>>>(A, Bw, bias, C, M, Nc, K, slope);
    };

    // init MLP: h0 = x @ W0 + b0
    gemm(x, W0, b0, h0, N, 128, 13, -1.f);

    // ---- GAT layer 1 ----
    gemm(h0, Wl1, bl1, xl, N, 256, 128, -1.f);
    gemm(h0, Wr1, br1, xr, N, 256, 128, -1.f);
    cudaMemsetAsync(agg, 0, (size_t)N * 256 * sizeof(float));
    cudaMemsetAsync(den, 0, (size_t)N * 4 * sizeof(float));
    init_keys<<<(N * 4 + 255) / 256, 256>>>(mkey, N * 4);
    gat_logit<<<(E + 31) / 32, 256, LOGIT_SMEM>>>(xl, xr, ea, ei, We1, att1, logit, mkey, E);
    gat_softmax_den<<<(E + 255) / 256, 256>>>(logit, ei, mkey, wbuf, den, E);
    gat_aggregate<<<(E * 32 + 255) / 256, 256>>>(xl, ei, wbuf, den, agg, E);
    add_bias<<<(N * 256 + 255) / 256, 256>>>(agg, bias1, h1, N * 256);

    // ---- GAT layer 2 ----
    gemm(h1, Wl2, bl2, xl, N, 256, 256, -1.f);
    gemm(h1, Wr2, br2, xr, N, 256, 256, -1.f);
    cudaMemsetAsync(agg, 0, (size_t)N * 256 * sizeof(float));
    cudaMemsetAsync(den, 0, (size_t)N * 4 * sizeof(float));
    init_keys<<<(N * 4 + 255) / 256, 256>>>(mkey, N * 4);
    gat_logit<<<(E + 31) / 32, 256, LOGIT_SMEM>>>(xl, xr, ea, ei, We2, att2, logit, mkey, E);
    gat_softmax_den<<<(E + 255) / 256, 256>>>(logit, ei, mkey, wbuf, den, E);
    gat_aggregate<<<(E * 32 + 255) / 256, 256>>>(xl, ei, wbuf, den, agg, E);
    add_bias<<<(N * 256 + 255) / 256, 256>>>(agg, bias2, h2, N * 256);

    // ---- attention pooling ----
    gemm(h2, Wp, bp, a, N, 256, 256, -1.f);
    cudaMemsetAsync(gsum, 0, (size_t)NB * 256 * sizeof(float));
    cudaMemsetAsync(gvec, 0, (size_t)NB * 256 * sizeof(float));
    init_keys<<<(NB * 256 + 255) / 256, 256>>>(gmkey, NB * 256);
    pool_max     <<<(N * 256 + 255) / 256, 256>>>(a, batch, gmkey, N * 256);
    pool_expsum  <<<(N * 256 + 255) / 256, 256>>>(a, batch, gmkey, gsum, N * 256);
    pool_weighted<<<(N * 256 + 255) / 256, 256>>>(h2, a, batch, gsum, gvec, N * 256);

    // ---- output MLP ----
    gemm(gvec, Wo1, bo1, y, NB, 256, 256, -1.f);
    bn_relu<<<1, 256>>>(y, gamma, beta, yact);
    gemm(yact, Wo2, bo2, out, NB, NOUT, 256, 0.01f);
}

// round 7
// speedup vs baseline: 1.3267x; 1.3267x over previous
#include <cuda_runtime.h>
#include <cuda_bf16.h>
#include <math.h>
#include <stdint.h>

#define MAXN 30000
#define MAXE 300000
#define NB   64
#define HC   256

// ---------------- scratch (device globals; no allocation allowed) ----------
__device__ float    g_h0  [MAXN*128];
__device__ float    g_xl  [MAXN*HC];
__device__ float    g_xr  [MAXN*HC];
__device__ float    g_h1  [MAXN*HC];
__device__ float    g_h2  [MAXN*HC];
__device__ float    g_agg [MAXN*HC];
__device__ float    g_logit[MAXE*4];
__device__ float    g_wbuf [MAXE*4];
__device__ unsigned g_mkey [MAXN*4];
__device__ float    g_den  [MAXN*4];
__device__ float    g_a   [MAXN*HC];
__device__ unsigned g_gmkey[NB*HC];
__device__ float    g_gsum [NB*HC];
__device__ float    g_gvec [NB*HC];
__device__ float    g_y   [NB*HC];
__device__ float    g_yact[NB*HC];
__device__ float    g_eaPad[(size_t)MAXE*64];   // padded edge_attr [E,64]
__device__ float    g_wtpool[7*65536];          // transposed weights, 7 slots

// ---------------- float <-> monotone unsigned key --------------------------
__device__ __forceinline__ unsigned fkey(float x) {
    unsigned u = __float_as_uint(x);
    return (u & 0x80000000u) ? ~u : (u | 0x80000000u);
}
__device__ __forceinline__ float funkey(unsigned k) {
    return (k & 0x80000000u) ? __uint_as_float(k ^ 0x80000000u)
                             : __uint_as_float(~k);
}
#define NEG_INF_KEY 0x007fffffu

// ---------------- bf16 mma.sync (plain PTX, works on compute_103) ----------
__device__ __forceinline__ void mma16816(float* d, const unsigned* a, const unsigned* b) {
    asm volatile(
        "mma.sync.aligned.m16n8k16.row.col.f32.bf16.bf16.f32 "
        "{%0,%1,%2,%3}, {%4,%5,%6,%7}, {%8,%9}, {%0,%1,%2,%3};"
        : "+f"(d[0]), "+f"(d[1]), "+f"(d[2]), "+f"(d[3])
        : "r"(a[0]), "r"(a[1]), "r"(a[2]), "r"(a[3]), "r"(b[0]), "r"(b[1]));
}

// ============================================================================
// bf16-split mma GEMM. C[M,256] = A[M,K] @ BT[256,K]^T (+ epilogue).
// Block: 128 rows x 128 cols (grid.x=2 covers 256 cols). 256 threads, 8 warps
// in 4(M) x 2(N); warp tile 32x64 = 2 x 8 m16n8k16 fragments.
// 2-term split: x = hi + lo (bf16 each); D += Ah*Bh + Ah*Bl + Al*Bh.
// GAT=0: C[row][col] = D + aux[col]  (aux = bias, ldc = 256)
// GAT=1: rows = edges. z = D + xl[src]+xr[dst]; leaky_relu(0.2); dot with
//        aux(=att) over the warp's 64-col head slab; C = logit[E][4]; atomicMax.
// ============================================================================
template <int GAT>
__global__ __launch_bounds__(256)
void gemm_mma(const float* __restrict__ A, const float* __restrict__ BT,
              const float* __restrict__ aux, float* __restrict__ C,
              int M, int K,
              const float* __restrict__ xl, const float* __restrict__ xr,
              const int* __restrict__ ei, unsigned* __restrict__ mkey, int E)
{
    __shared__ __nv_bfloat16 As_hi[128][36];
    __shared__ __nv_bfloat16 As_lo[128][36];
    __shared__ __nv_bfloat16 Bs_hi[128][36];
    __shared__ __nv_bfloat16 Bs_lo[128][36];
    __shared__ float sAux[128];

    const int tid = threadIdx.x;
    const int lane = tid & 31, wid = tid >> 5;
    const int warpM = wid & 3, warpN = wid >> 2;
    const int tRow = lane >> 2;          // 0..7
    const int tCol = (lane & 3) * 2;     // 0,2,4,6
    const int rowBase = blockIdx.y * 128;
    const int colBase = blockIdx.x * 128;

    if (tid < 128) sAux[tid] = aux[colBase + tid];

    float acc[2][8][4];
#pragma unroll
    for (int mt = 0; mt < 2; mt++)
#pragma unroll
        for (int nt = 0; nt < 8; nt++)
#pragma unroll
            for (int j = 0; j < 4; j++) acc[mt][nt][j] = 0.f;

    const int nk = K >> 5;   // K multiple of 32
    for (int kt = 0; kt < nk; kt++) {
        const int kOff = kt * 32;
        // ---- load + split tiles ----
#pragma unroll
        for (int i = 0; i < 4; i++) {
            int g = tid + i * 256;           // 0..1023
            int r = g >> 3, c4 = (g & 7) * 4;
            // A
            float4 v = make_float4(0.f, 0.f, 0.f, 0.f);
            int gr = rowBase + r;
            if (gr < M) v = *(const float4*)(A + (size_t)gr * K + kOff + c4);
            {
                __nv_bfloat16 hx = __float2bfloat16(v.x);
                __nv_bfloat16 hy = __float2bfloat16(v.y);
                __nv_bfloat16 hz = __float2bfloat16(v.z);
                __nv_bfloat16 hw = __float2bfloat16(v.w);
                As_hi[r][c4+0] = hx; As_hi[r][c4+1] = hy;
                As_hi[r][c4+2] = hz; As_hi[r][c4+3] = hw;
                As_lo[r][c4+0] = __float2bfloat16(v.x - __bfloat162float(hx));
                As_lo[r][c4+1] = __float2bfloat16(v.y - __bfloat162float(hy));
                As_lo[r][c4+2] = __float2bfloat16(v.z - __bfloat162float(hz));
                As_lo[r][c4+3] = __float2bfloat16(v.w - __bfloat162float(hw));
            }
            // B (BT is always [256][K], no row guard needed)
            float4 w = *(const float4*)(BT + (size_t)(colBase + r) * K + kOff + c4);
            {
                __nv_bfloat16 hx = __float2bfloat16(w.x);
                __nv_bfloat16 hy = __float2bfloat16(w.y);
                __nv_bfloat16 hz = __float2bfloat16(w.z);
                __nv_bfloat16 hw = __float2bfloat16(w.w);
                Bs_hi[r][c4+0] = hx; Bs_hi[r][c4+1] = hy;
                Bs_hi[r][c4+2] = hz; Bs_hi[r][c4+3] = hw;
                Bs_lo[r][c4+0] = __float2bfloat16(w.x - __bfloat162float(hx));
                Bs_lo[r][c4+1] = __float2bfloat16(w.y - __bfloat162float(hy));
                Bs_lo[r][c4+2] = __float2bfloat16(w.z - __bfloat162float(hz));
                Bs_lo[r][c4+3] = __float2bfloat16(w.w - __bfloat162float(hw));
            }
        }
        __syncthreads();
        // ---- compute: 2 x k16 ----
#pragma unroll
        for (int ks = 0; ks < 2; ks++) {
            const int k0 = ks * 16;
            unsigned bh[8][2], bl[8][2];
#pragma unroll
            for (int nt = 0; nt < 8; nt++) {
                int n = 64 * warpN + 8 * nt + tRow;
                bh[nt][0] = *(const unsigned*)&Bs_hi[n][k0 + tCol];
                bh[nt][1] = *(const unsigned*)&Bs_hi[n][k0 + tCol + 8];
                bl[nt][0] = *(const unsigned*)&Bs_lo[n][k0 + tCol];
                bl[nt][1] = *(const unsigned*)&Bs_lo[n][k0 + tCol + 8];
            }
#pragma unroll
            for (int mt = 0; mt < 2; mt++) {
                int r = 32 * warpM + 16 * mt + tRow;
                unsigned ah[4], al[4];
                ah[0] = *(const unsigned*)&As_hi[r    ][k0 + tCol];
                ah[1] = *(const unsigned*)&As_hi[r + 8][k0 + tCol];
                ah[2] = *(const unsigned*)&As_hi[r    ][k0 + tCol + 8];
                ah[3] = *(const unsigned*)&As_hi[r + 8][k0 + tCol + 8];
                al[0] = *(const unsigned*)&As_lo[r    ][k0 + tCol];
                al[1] = *(const unsigned*)&As_lo[r + 8][k0 + tCol];
                al[2] = *(const unsigned*)&As_lo[r    ][k0 + tCol + 8];
                al[3] = *(const unsigned*)&As_lo[r + 8][k0 + tCol + 8];
#pragma unroll
                for (int nt = 0; nt < 8; nt++) {
                    mma16816(acc[mt][nt], ah, bh[nt]);
                    mma16816(acc[mt][nt], ah, bl[nt]);
                    mma16816(acc[mt][nt], al, bh[nt]);
                }
            }
        }
        __syncthreads();
    }

    // ---- epilogue ----
    if (GAT == 0) {
#pragma unroll
        for (int mt = 0; mt < 2; mt++) {
            int r0 = rowBase + 32 * warpM + 16 * mt + tRow;
#pragma unroll
            for (int nt = 0; nt < 8; nt++) {
                int cl = 64 * warpN + 8 * nt + tCol;
                int cg = colBase + cl;
                if (r0 < M) {
                    float2 o = make_float2(acc[mt][nt][0] + sAux[cl],
                                           acc[mt][nt][1] + sAux[cl + 1]);
                    *(float2*)(C + (size_t)r0 * 256 + cg) = o;
                }
                if (r0 + 8 < M) {
                    float2 o = make_float2(acc[mt][nt][2] + sAux[cl],
                                           acc[mt][nt][3] + sAux[cl + 1]);
                    *(float2*)(C + (size_t)(r0 + 8) * 256 + cg) = o;
                }
            }
        }
    } else {
        const int h = (colBase + 64 * warpN) >> 6;   // head for this warp's slab
#pragma unroll
        for (int mt = 0; mt < 2; mt++) {
            int e0 = rowBase + 32 * warpM + 16 * mt + tRow;
            int e1 = e0 + 8;
            bool v0 = e0 < E, v1 = e1 < E;
            int s0 = v0 ? ei[e0] : 0, d0 = v0 ? ei[E + e0] : 0;
            int s1 = v1 ? ei[e1] : 0, d1 = v1 ? ei[E + e1] : 0;
            float p0 = 0.f, p1 = 0.f;
#pragma unroll
            for (int nt = 0; nt < 8; nt++) {
                int cl = 64 * warpN + 8 * nt + tCol;
                int cg = colBase + cl;
                float a0 = sAux[cl], a1 = sAux[cl + 1];
                if (v0) {
                    float2 lv = *(const float2*)(xl + (size_t)s0 * 256 + cg);
                    float2 rv = *(const float2*)(xr + (size_t)d0 * 256 + cg);
                    float z0 = acc[mt][nt][0] + lv.x + rv.x;
                    float z1 = acc[mt][nt][1] + lv.y + rv.y;
                    z0 = z0 > 0.f ? z0 : 0.2f * z0;
                    z1 = z1 > 0.f ? z1 : 0.2f * z1;
                    p0 += a0 * z0 + a1 * z1;
                }
                if (v1) {
                    float2 lv = *(const float2*)(xl + (size_t)s1 * 256 + cg);
                    float2 rv = *(const float2*)(xr + (size_t)d1 * 256 + cg);
                    float z0 = acc[mt][nt][2] + lv.x + rv.x;
                    float z1 = acc[mt][nt][3] + lv.y + rv.y;
                    z0 = z0 > 0.f ? z0 : 0.2f * z0;
                    z1 = z1 > 0.f ? z1 : 0.2f * z1;
                    p1 += a0 * z0 + a1 * z1;
                }
            }
            // reduce over the quad (lanes sharing tRow)
            p0 += __shfl_xor_sync(0xffffffffu, p0, 1);
            p0 += __shfl_xor_sync(0xffffffffu, p0, 2);
            p1 += __shfl_xor_sync(0xffffffffu, p1, 1);
            p1 += __shfl_xor_sync(0xffffffffu, p1, 2);
            if ((lane & 3) == 0) {
                if (v0) {
                    C[(size_t)e0 * 4 + h] = p0;
                    atomicMax(mkey + (size_t)d0 * 4 + h, fkey(p0));
                }
                if (v1) {
                    C[(size_t)e1 * 4 + h] = p1;
                    atomicMax(mkey + (size_t)d1 * 4 + h, fkey(p1));
                }
            }
        }
    }
}

// ---------------- generic tiled fp32 GEMM (small cases) ---------------------
__global__ void gemm_bias(const float* __restrict__ A, const float* __restrict__ Bw,
                          const float* __restrict__ bias, float* __restrict__ C,
                          int M, int N, int K, float slope)
{
    __shared__ __align__(16) float As[16][128];
    __shared__ __align__(16) float Bs[16][64];
    int t  = threadIdx.x;
    int tx = t & 15;
    int ty = t >> 4;
    int rowBase = blockIdx.y * 128;
    int colBase = blockIdx.x * 64;

    float acc[8][4];
#pragma unroll
    for (int i = 0; i < 8; i++)
#pragma unroll
        for (int j = 0; j < 4; j++) acc[i][j] = 0.f;

    int nk = (K + 15) / 16;
    bool kvec = ((K & 15) == 0);
    for (int kt = 0; kt < nk; kt++) {
        int k0 = kt * 16;
        if (kvec) {
#pragma unroll
            for (int r = 0; r < 2; r++) {
                int i = t + r * 256;
                int m = i >> 2, kq = i & 3;
                int gm = rowBase + m;
                float4 v = make_float4(0.f, 0.f, 0.f, 0.f);
                if (gm < M) v = *(const float4*)(A + (long long)gm * K + k0 + kq * 4);
                As[kq*4+0][m] = v.x; As[kq*4+1][m] = v.y;
                As[kq*4+2][m] = v.z; As[kq*4+3][m] = v.w;
            }
        } else {
#pragma unroll
            for (int r = 0; r < 8; r++) {
                int i = t + r * 256;
                int m = i >> 4, kk = i & 15;
                int gm = rowBase + m, gk = k0 + kk;
                As[kk][m] = (gm < M && gk < K) ? A[(long long)gm * K + gk] : 0.f;
            }
        }
#pragma unroll
        for (int r = 0; r < 4; r++) {
            int i = t + r * 256;
            int kk = i >> 6, nn = i & 63;
            int gk = k0 + kk, gn = colBase + nn;
            Bs[kk][nn] = (gk < K && gn < N) ? Bw[(long long)gk * N + gn] : 0.f;
        }
        __syncthreads();
#pragma unroll
        for (int kk = 0; kk < 16; kk++) {
            float4 b4 = *(const float4*)&Bs[kk][tx * 4];
            float4 a0 = *(const float4*)&As[kk][ty * 8];
            float4 a1 = *(const float4*)&As[kk][ty * 8 + 4];
            float av[8] = {a0.x, a0.y, a0.z, a0.w, a1.x, a1.y, a1.z, a1.w};
            float bv[4] = {b4.x, b4.y, b4.z, b4.w};
#pragma unroll
            for (int i = 0; i < 8; i++)
#pragma unroll
                for (int j = 0; j < 4; j++) acc[i][j] += av[i] * bv[j];
        }
        __syncthreads();
    }
#pragma unroll
    for (int i = 0; i < 8; i++) {
        int gm = rowBase + ty * 8 + i;
        if (gm >= M) continue;
#pragma unroll
        for (int j = 0; j < 4; j++) {
            int gn = colBase + tx * 4 + j;
            if (gn >= N) continue;
            float v = acc[i][j] + bias[gn];
            if (slope >= 0.f) v = v > 0.f ? v : v * slope;
            C[(long long)gm * N + gn] = v;
        }
    }
}

// ---------------- small prep kernels ---------------------------------------
__global__ void init_keys(unsigned* __restrict__ k, int n) {
    int i = blockIdx.x * blockDim.x + threadIdx.x;
    if (i < n) k[i] = NEG_INF_KEY;
}
// out[n*Kout + k] = (k < Kin) ? in[k*Ncols + n] : 0   (transpose + K pad)
__global__ void transpose_pad(const float* __restrict__ in, float* __restrict__ out,
                              int Kin, int Kout, int Ncols)
{
    int i = blockIdx.x * blockDim.x + threadIdx.x;
    if (i >= Ncols * Kout) return;
    int n = i / Kout, k = i % Kout;
    out[i] = (k < Kin) ? in[(size_t)k * Ncols + n] : 0.f;
}
__global__ void pad_ea(const float* __restrict__ ea, float* __restrict__ out, int E) {
    int i = blockIdx.x * blockDim.x + threadIdx.x;
    if (i >= E * 64) return;
    int e = i >> 6, k = i & 63;
    out[i] = (k < 51) ? ea[(size_t)e * 51 + k] : 0.f;
}

// ---------------- softmax denominator --------------------------------------
__global__ void gat_softmax_den(const float* __restrict__ logit,
                                const int* __restrict__ ei,
                                const unsigned* __restrict__ mkey,
                                float* __restrict__ w, float* __restrict__ den, int E)
{
    int e = blockIdx.x * blockDim.x + threadIdx.x;
    if (e >= E) return;
    int d = ei[(long long)E + e];
    float4 lg = *(const float4*)(logit + (long long)e * 4);
    float m0 = funkey(mkey[d * 4 + 0]);
    float m1 = funkey(mkey[d * 4 + 1]);
    float m2 = funkey(mkey[d * 4 + 2]);
    float m3 = funkey(mkey[d * 4 + 3]);
    float w0 = expf(lg.x - m0), w1 = expf(lg.y - m1);
    float w2 = expf(lg.z - m2), w3 = expf(lg.w - m3);
    *(float4*)(w + (long long)e * 4) = make_float4(w0, w1, w2, w3);
    atomicAdd(&den[d * 4 + 0], w0);
    atomicAdd(&den[d * 4 + 1], w1);
    atomicAdd(&den[d * 4 + 2], w2);
    atomicAdd(&den[d * 4 + 3], w3);
}

// ---------------- weighted aggregation (warp per edge) ---------------------
__global__ void gat_aggregate(const float* __restrict__ xl,
                              const int* __restrict__ ei,
                              const float* __restrict__ w, const float* __restrict__ den,
                              float* __restrict__ agg, int E)
{
    int gw = (blockIdx.x * blockDim.x + threadIdx.x) >> 5;
    int lane = threadIdx.x & 31;
    if (gw >= E) return;
    long long e = gw;
    int s = ei[e], d = ei[(long long)E + e];
    int hA = lane >> 4, hB = 2 + hA;
    float aA = w[e * 4 + hA] / (den[(long long)d * 4 + hA] + 1e-16f);
    float aB = w[e * 4 + hB] / (den[(long long)d * 4 + hB] + 1e-16f);
    int cA = lane * 4, cB = 128 + lane * 4;
    float4 xA = *(const float4*)(xl + (long long)s * 256 + cA);
    float4 xB = *(const float4*)(xl + (long long)s * 256 + cB);
    float* dp = agg + (long long)d * 256;
    atomicAdd(dp + cA + 0, xA.x * aA);
    atomicAdd(dp + cA + 1, xA.y * aA);
    atomicAdd(dp + cA + 2, xA.z * aA);
    atomicAdd(dp + cA + 3, xA.w * aA);
    atomicAdd(dp + cB + 0, xB.x * aB);
    atomicAdd(dp + cB + 1, xB.y * aB);
    atomicAdd(dp + cB + 2, xB.z * aB);
    atomicAdd(dp + cB + 3, xB.w * aB);
}

__global__ void add_bias(const float* __restrict__ acc, const float* __restrict__ bias,
                         float* __restrict__ out, int total)
{
    int i = blockIdx.x * blockDim.x + threadIdx.x;
    if (i < total) out[i] = acc[i] + bias[i & 255];
}

// ---------------- pooling --------------------------------------------------
__global__ void pool_max(const float* __restrict__ a, const int* __restrict__ batch,
                         unsigned* __restrict__ keys, int total)
{
    int i = blockIdx.x * blockDim.x + threadIdx.x;
    if (i >= total) return;
    int b = batch[i >> 8];
    atomicMax(&keys[b * 256 + (i & 255)], fkey(a[i]));
}
__global__ void pool_expsum(float* __restrict__ a, const int* __restrict__ batch,
                            const unsigned* __restrict__ keys, float* __restrict__ gsum,
                            int total)
{
    int i = blockIdx.x * blockDim.x + threadIdx.x;
    if (i >= total) return;
    int b = batch[i >> 8];
    int c = i & 255;
    float wv = expf(a[i] - funkey(keys[b * 256 + c]));
    a[i] = wv;
    atomicAdd(&gsum[b * 256 + c], wv);
}
__global__ void pool_weighted(const float* __restrict__ h, const float* __restrict__ a,
                              const int* __restrict__ batch,
                              const float* __restrict__ gsum, float* __restrict__ g,
                              int total)
{
    int i = blockIdx.x * blockDim.x + threadIdx.x;
    if (i >= total) return;
    int b = batch[i >> 8];
    int c = i & 255;
    float attw = a[i] / (gsum[b * 256 + c] + 1e-16f);
    atomicAdd(&g[b * 256 + c], h[i] * attw);
}

// ---------------- batchnorm (train stats) + relu ---------------------------
__global__ void bn_relu(const float* __restrict__ y, const float* __restrict__ gamma,
                        const float* __restrict__ beta, float* __restrict__ yact)
{
    int c = threadIdx.x;
    float s = 0.f, s2 = 0.f;
    for (int m = 0; m < NB; m++) {
        float v = y[m * 256 + c];
        s += v; s2 += v * v;
    }
    float mu = s * (1.f / NB);
    float var = s2 * (1.f / NB) - mu * mu;
    float inv = rsqrtf(var + 1e-5f);
    float ga = gamma[c], be = beta[c];
    for (int m = 0; m < NB; m++) {
        float v = (y[m * 256 + c] - mu) * inv * ga + be;
        yact[m * 256 + c] = v > 0.f ? v : 0.f;
    }
}

// ---------------- launcher --------------------------------------------------
extern "C" void kernel_launch(void* const* d_in, const int* in_sizes, int n_in,
                              void* d_out, int out_size)
{
    const float* x     = (const float*)d_in[0];
    const int*   ei    = (const int*)d_in[1];
    const float* ea    = (const float*)d_in[2];
    const int*   batch = (const int*)d_in[3];
    const float* W0   = (const float*)d_in[4];  const float* b0   = (const float*)d_in[5];
    const float* Wl1  = (const float*)d_in[6];  const float* bl1  = (const float*)d_in[7];
    const float* Wr1  = (const float*)d_in[8];  const float* br1  = (const float*)d_in[9];
    const float* We1  = (const float*)d_in[10]; const float* att1 = (const float*)d_in[11];
    const float* bias1= (const float*)d_in[12];
    const float* Wl2  = (const float*)d_in[13]; const float* bl2  = (const float*)d_in[14];
    const float* Wr2  = (const float*)d_in[15]; const float* br2  = (const float*)d_in[16];
    const float* We2  = (const float*)d_in[17]; const float* att2 = (const float*)d_in[18];
    const float* bias2= (const float*)d_in[19];
    const float* Wp   = (const float*)d_in[20]; const float* bp   = (const float*)d_in[21];
    const float* Wo1  = (const float*)d_in[22]; const float* bo1  = (const float*)d_in[23];
    const float* gamma= (const float*)d_in[24]; const float* beta = (const float*)d_in[25];
    const float* Wo2  = (const float*)d_in[26]; const float* bo2  = (const float*)d_in[27];
    float* out = (float*)d_out;

    const int N = in_sizes[0] / 13;
    const int E = in_sizes[2] / 51;
    const int NOUT = in_sizes[26] / 256;   // 2001

    float *h0, *xl, *xr, *h1, *h2, *agg, *logit, *wbuf, *den, *a, *gsum, *gvec, *y, *yact;
    float *eaPad, *wt;
    unsigned *mkey, *gmkey;
    cudaGetSymbolAddress((void**)&h0,   g_h0);
    cudaGetSymbolAddress((void**)&xl,   g_xl);
    cudaGetSymbolAddress((void**)&xr,   g_xr);
    cudaGetSymbolAddress((void**)&h1,   g_h1);
    cudaGetSymbolAddress((void**)&h2,   g_h2);
    cudaGetSymbolAddress((void**)&agg,  g_agg);
    cudaGetSymbolAddress((void**)&logit,g_logit);
    cudaGetSymbolAddress((void**)&wbuf, g_wbuf);
    cudaGetSymbolAddress((void**)&mkey, g_mkey);
    cudaGetSymbolAddress((void**)&den,  g_den);
    cudaGetSymbolAddress((void**)&a,    g_a);
    cudaGetSymbolAddress((void**)&gmkey,g_gmkey);
    cudaGetSymbolAddress((void**)&gsum, g_gsum);
    cudaGetSymbolAddress((void**)&gvec, g_gvec);
    cudaGetSymbolAddress((void**)&y,    g_y);
    cudaGetSymbolAddress((void**)&yact, g_yact);
    cudaGetSymbolAddress((void**)&eaPad, g_eaPad);
    cudaGetSymbolAddress((void**)&wt,   g_wtpool);

    float* wtL1 = wt + 0 * 65536;
    float* wtR1 = wt + 1 * 65536;
    float* wtL2 = wt + 2 * 65536;
    float* wtR2 = wt + 3 * 65536;
    float* wtP  = wt + 4 * 65536;
    float* wtE1 = wt + 5 * 65536;
    float* wtE2 = wt + 6 * 65536;

    const int Et = (E + 127) / 128;

    auto gemmF = [&](const float* A, const float* Bw, const float* bias, float* C,
                     int M, int Nc, int K, float slope) {
        dim3 grid((Nc + 63) / 64, (M + 127) / 128);
        gemm_bias<<<grid, 256>>>(A, Bw, bias, C, M, Nc, K, slope);
    };
    auto gemmT = [&](const float* A, const float* BT, const float* bias, float* C,
                     int M, int K) {
        gemm_mma<0><<<dim3(2, (M + 127) / 128), 256>>>(
            A, BT, bias, C, M, K, nullptr, nullptr, nullptr, nullptr, 0);
    };

    // ---- prep: transposed weights + padded edge_attr ----
    transpose_pad<<<(256*128 + 255)/256, 256>>>(Wl1, wtL1, 128, 128, 256);
    transpose_pad<<<(256*128 + 255)/256, 256>>>(Wr1, wtR1, 128, 128, 256);
    transpose_pad<<<(256*256 + 255)/256, 256>>>(Wl2, wtL2, 256, 256, 256);
    transpose_pad<<<(256*256 + 255)/256, 256>>>(Wr2, wtR2, 256, 256, 256);
    transpose_pad<<<(256*256 + 255)/256, 256>>>(Wp,  wtP,  256, 256, 256);
    transpose_pad<<<(256*64  + 255)/256, 256>>>(We1, wtE1, 51, 64, 256);
    transpose_pad<<<(256*64  + 255)/256, 256>>>(We2, wtE2, 51, 64, 256);
    pad_ea<<<(E*64 + 255)/256, 256>>>(ea, eaPad, E);

    // init MLP: h0 = x @ W0 + b0 (K=13, fp32)
    gemmF(x, W0, b0, h0, N, 128, 13, -1.f);

    // ---- GAT layer 1 ----
    gemmT(h0, wtL1, bl1, xl, N, 128);
    gemmT(h0, wtR1, br1, xr, N, 128);
    cudaMemsetAsync(agg, 0, (size_t)N * 256 * sizeof(float));
    cudaMemsetAsync(den, 0, (size_t)N * 4 * sizeof(float));
    init_keys<<<(N * 4 + 255) / 256, 256>>>(mkey, N * 4);
    gemm_mma<1><<<dim3(2, Et), 256>>>(
        eaPad, wtE1, att1, logit, E, 64, xl, xr, ei, mkey, E);
    gat_softmax_den<<<(E + 255) / 256, 256>>>(logit, ei, mkey, wbuf, den, E);
    gat_aggregate<<<(E * 32 + 255) / 256, 256>>>(xl, ei, wbuf, den, agg, E);
    add_bias<<<(N * 256 + 255) / 256, 256>>>(agg, bias1, h1, N * 256);

    // ---- GAT layer 2 ----
    gemmT(h1, wtL2, bl2, xl, N, 256);
    gemmT(h1, wtR2, br2, xr, N, 256);
    cudaMemsetAsync(agg, 0, (size_t)N * 256 * sizeof(float));
    cudaMemsetAsync(den, 0, (size_t)N * 4 * sizeof(float));
    init_keys<<<(N * 4 + 255) / 256, 256>>>(mkey, N * 4);
    gemm_mma<1><<<dim3(2, Et), 256>>>(
        eaPad, wtE2, att2, logit, E, 64, xl, xr, ei, mkey, E);
    gat_softmax_den<<<(E + 255) / 256, 256>>>(logit, ei, mkey, wbuf, den, E);
    gat_aggregate<<<(E * 32 + 255) / 256, 256>>>(xl, ei, wbuf, den, agg, E);
    add_bias<<<(N * 256 + 255) / 256, 256>>>(agg, bias2, h2, N * 256);

    // ---- attention pooling ----
    gemmT(h2, wtP, bp, a, N, 256);
    cudaMemsetAsync(gsum, 0, (size_t)NB * 256 * sizeof(float));
    cudaMemsetAsync(gvec, 0, (size_t)NB * 256 * sizeof(float));
    init_keys<<<(NB * 256 + 255) / 256, 256>>>(gmkey, NB * 256);
    pool_max     <<<(N * 256 + 255) / 256, 256>>>(a, batch, gmkey, N * 256);
    pool_expsum  <<<(N * 256 + 255) / 256, 256>>>(a, batch, gmkey, gsum, N * 256);
    pool_weighted<<<(N * 256 + 255) / 256, 256>>>(h2, a, batch, gsum, gvec, N * 256);

    // ---- output MLP (small, fp32) ----
    gemmF(gvec, Wo1, bo1, y, NB, 256, 256, -1.f);
    bn_relu<<<1, 256>>>(y, gamma, beta, yact);
    gemmF(yact, Wo2, bo2, out, NB, NOUT, 256, 0.01f);
}

// round 10
// speedup vs baseline: 1.4562x; 1.0976x over previous
#include <cuda_runtime.h>
#include <cuda_bf16.h>
#include <math.h>
#include <stdint.h>

#define MAXN 30000
#define MAXE 300000
#define NB   64
#define HC   256

// ---------------- scratch (device globals; no allocation allowed) ----------
__device__ float         g_h0  [MAXN*128];
__device__ float         g_xl  [MAXN*HC];
__device__ float         g_xr  [MAXN*HC];
__device__ float         g_h1  [MAXN*HC];
__device__ float         g_h2  [MAXN*HC];
__device__ float         g_agg [MAXN*HC];
__device__ float         g_logit[MAXE*4];
__device__ unsigned      g_mkey [MAXN*4];
__device__ float         g_den  [MAXN*4];
__device__ float         g_a   [MAXN*HC];
__device__ unsigned      g_gmkey[NB*HC];
__device__ float         g_gsum [NB*HC];
__device__ float         g_gvec [NB*HC];
__device__ float         g_y   [NB*HC];
__device__ float         g_yact[NB*HC];
__device__ __nv_bfloat16 g_h0h [MAXN*128];
__device__ __nv_bfloat16 g_h0l [MAXN*128];
__device__ __nv_bfloat16 g_hh  [MAXN*HC];
__device__ __nv_bfloat16 g_hl  [MAXN*HC];
__device__ __nv_bfloat16 g_eah [(size_t)MAXE*64];
__device__ __nv_bfloat16 g_eal [(size_t)MAXE*64];
__device__ __nv_bfloat16 g_wth [7*65536];
__device__ __nv_bfloat16 g_wtl [7*65536];

// ---------------- float <-> monotone unsigned key --------------------------
__device__ __forceinline__ unsigned fkey(float x) {
    unsigned u = __float_as_uint(x);
    return (u & 0x80000000u) ? ~u : (u | 0x80000000u);
}
__device__ __forceinline__ float funkey(unsigned k) {
    return (k & 0x80000000u) ? __uint_as_float(k ^ 0x80000000u)
                             : __uint_as_float(~k);
}
#define NEG_INF_KEY 0x007fffffu

// ---------------- PTX helpers ----------------------------------------------
__device__ __forceinline__ void mma16816(float* d, const unsigned* a, const unsigned* b) {
    asm volatile(
        "mma.sync.aligned.m16n8k16.row.col.f32.bf16.bf16.f32 "
        "{%0,%1,%2,%3}, {%4,%5,%6,%7}, {%8,%9}, {%0,%1,%2,%3};"
        : "+f"(d[0]), "+f"(d[1]), "+f"(d[2]), "+f"(d[3])
        : "r"(a[0]), "r"(a[1]), "r"(a[2]), "r"(a[3]), "r"(b[0]), "r"(b[1]));
}
__device__ __forceinline__ void ldm4(unsigned addr, unsigned* r) {
    asm volatile("ldmatrix.sync.aligned.m8n8.x4.shared.b16 {%0,%1,%2,%3}, [%4];"
        : "=r"(r[0]), "=r"(r[1]), "=r"(r[2]), "=r"(r[3]) : "r"(addr));
}
__device__ __forceinline__ void cp16(unsigned dst, const void* src, int sz) {
    asm volatile("cp.async.cg.shared.global [%0], [%1], 16, %2;"
        :: "r"(dst), "l"(src), "r"(sz));
}
__device__ __forceinline__ unsigned smem_u32(const void* p) {
    unsigned a;
    asm("{ .reg .u64 t; cvta.to.shared.u64 t, %1; cvt.u32.u64 %0, t; }"
        : "=r"(a) : "l"(p));
    return a;
}

// smem geometry: per stage 4 tiles (Ah, Al, Bh, Bl), each 128 rows x 32 bf16
// with row stride 40 bf16 (80 B) -> 10240 B per tile, 40960 B per stage.
#define TILE_B   10240
#define STAGE_B  40960
#define GEMM_SMEM (2 * STAGE_B)

// ============================================================================
// Split-bf16 mma GEMM with cp.async double buffering + ldmatrix.
// C[M,256] = (Ah+Al)[M,K] @ ((Bh+Bl)[256,K])^T, 3-term split products.
// Block 128x128 (grid.x=2 covers 256 cols), 256 thr, 8 warps 4(M)x2(N),
// warp tile 32x64 = 2x8 m16n8k16.
// GAT=0: C[r][c] = D + aux[c].
// GAT=1: rows=edges; z = D + xl[src]+xr[dst]; lrelu(0.2); head-dot with aux;
//        C=logit[E][4]; atomicMax mkey.
// ============================================================================
template <int GAT>
__global__ __launch_bounds__(256)
void gemm_mma(const __nv_bfloat16* __restrict__ Ah, const __nv_bfloat16* __restrict__ Al,
              const __nv_bfloat16* __restrict__ Bh, const __nv_bfloat16* __restrict__ Bl,
              const float* __restrict__ aux, float* __restrict__ C,
              int M, int K,
              const float* __restrict__ xl, const float* __restrict__ xr,
              const int* __restrict__ ei, unsigned* __restrict__ mkey, int E)
{
    extern __shared__ __align__(16) char dsm[];
    __shared__ float sAux[128];
    const unsigned sb = smem_u32(dsm);

    const int tid = threadIdx.x;
    const int lane = tid & 31, wid = tid >> 5;
    const int warpM = wid & 3, warpN = wid >> 2;
    const int tRow = lane >> 2;
    const int tCol = (lane & 3) * 2;
    const int rowBase = blockIdx.y * 128;
    const int colBase = blockIdx.x * 128;
    const int l8 = lane & 7, m4 = lane >> 3;   // ldmatrix lane split

    if (tid < 128) sAux[tid] = aux[colBase + tid];

    float acc[2][8][4];
#pragma unroll
    for (int mt = 0; mt < 2; mt++)
#pragma unroll
        for (int nt = 0; nt < 8; nt++)
#pragma unroll
            for (int j = 0; j < 4; j++) acc[mt][nt][j] = 0.f;

    const int nk = K >> 5;

    auto issue_stage = [&](int kt) {
        const int s = kt & 1;
        const int kOff = kt * 32;
        const unsigned base = sb + s * STAGE_B;
#pragma unroll
        for (int half = 0; half < 2; half++) {
            int ch = tid + half * 256;          // 0..511
            int r = ch >> 2, c16 = ch & 3;
            unsigned doff = (unsigned)(r * 80 + c16 * 16);
            // A (guard rows)
            int gr = rowBase + r;
            bool v = gr < M;
            size_t aoff = (size_t)(v ? gr : 0) * K + kOff + c16 * 8;
            cp16(base + doff,          Ah + aoff, v ? 16 : 0);
            cp16(base + TILE_B + doff, Al + aoff, v ? 16 : 0);
            // B (always 256 rows)
            size_t boff = (size_t)(colBase + r) * K + kOff + c16 * 8;
            cp16(base + 2 * TILE_B + doff, Bh + boff, 16);
            cp16(base + 3 * TILE_B + doff, Bl + boff, 16);
        }
        asm volatile("cp.async.commit_group;");
    };

    issue_stage(0);

    for (int kt = 0; kt < nk; kt++) {
        if (kt + 1 < nk) {
            issue_stage(kt + 1);
            asm volatile("cp.async.wait_group 1;");
        } else {
            asm volatile("cp.async.wait_group 0;");
        }
        __syncthreads();

        const unsigned base = sb + (kt & 1) * STAGE_B;
#pragma unroll
        for (int ks = 0; ks < 2; ks++) {
            const int k0 = ks * 16;
            unsigned bh[8][2], bl[8][2];
#pragma unroll
            for (int np = 0; np < 4; np++) {
                int row = 64 * warpN + 16 * np + (m4 & 1) * 8 + l8;
                int col = k0 + (m4 >> 1) * 8;
                unsigned addr = base + 2 * TILE_B + row * 80 + col * 2;
                unsigned r4[4];
                ldm4(addr, r4);
                bh[2*np][0] = r4[0]; bh[2*np+1][0] = r4[1];
                bh[2*np][1] = r4[2]; bh[2*np+1][1] = r4[3];
                ldm4(addr + TILE_B, r4);
                bl[2*np][0] = r4[0]; bl[2*np+1][0] = r4[1];
                bl[2*np][1] = r4[2]; bl[2*np+1][1] = r4[3];
            }
#pragma unroll
            for (int mt = 0; mt < 2; mt++) {
                int row = 32 * warpM + 16 * mt + (m4 & 1) * 8 + l8;
                int col = k0 + (m4 >> 1) * 8;
                unsigned addr = base + row * 80 + col * 2;
                unsigned ah[4], al[4];
                ldm4(addr, ah);
                ldm4(addr + TILE_B, al);
#pragma unroll
                for (int nt = 0; nt < 8; nt++) {
                    mma16816(acc[mt][nt], ah, bh[nt]);
                    mma16816(acc[mt][nt], ah, bl[nt]);
                    mma16816(acc[mt][nt], al, bh[nt]);
                }
            }
        }
        __syncthreads();
    }

    // ---- epilogue ----
    if (GAT == 0) {
#pragma unroll
        for (int mt = 0; mt < 2; mt++) {
            int r0 = rowBase + 32 * warpM + 16 * mt + tRow;
#pragma unroll
            for (int nt = 0; nt < 8; nt++) {
                int cl = 64 * warpN + 8 * nt + tCol;
                int cg = colBase + cl;
                if (r0 < M) {
                    float2 o = make_float2(acc[mt][nt][0] + sAux[cl],
                                           acc[mt][nt][1] + sAux[cl + 1]);
                    *(float2*)(C + (size_t)r0 * 256 + cg) = o;
                }
                if (r0 + 8 < M) {
                    float2 o = make_float2(acc[mt][nt][2] + sAux[cl],
                                           acc[mt][nt][3] + sAux[cl + 1]);
                    *(float2*)(C + (size_t)(r0 + 8) * 256 + cg) = o;
                }
            }
        }
    } else {
        const int h = (colBase + 64 * warpN) >> 6;
#pragma unroll
        for (int mt = 0; mt < 2; mt++) {
            int e0 = rowBase + 32 * warpM + 16 * mt + tRow;
            int e1 = e0 + 8;
            bool v0 = e0 < E, v1 = e1 < E;
            int s0 = v0 ? ei[e0] : 0, d0 = v0 ? ei[E + e0] : 0;
            int s1 = v1 ? ei[e1] : 0, d1 = v1 ? ei[E + e1] : 0;
            float p0 = 0.f, p1 = 0.f;
#pragma unroll
            for (int nt = 0; nt < 8; nt++) {
                int cl = 64 * warpN + 8 * nt + tCol;
                int cg = colBase + cl;
                float a0 = sAux[cl], a1 = sAux[cl + 1];
                if (v0) {
                    float2 lv = *(const float2*)(xl + (size_t)s0 * 256 + cg);
                    float2 rv = *(const float2*)(xr + (size_t)d0 * 256 + cg);
                    float z0 = acc[mt][nt][0] + lv.x + rv.x;
                    float z1 = acc[mt][nt][1] + lv.y + rv.y;
                    z0 = z0 > 0.f ? z0 : 0.2f * z0;
                    z1 = z1 > 0.f ? z1 : 0.2f * z1;
                    p0 += a0 * z0 + a1 * z1;
                }
                if (v1) {
                    float2 lv = *(const float2*)(xl + (size_t)s1 * 256 + cg);
                    float2 rv = *(const float2*)(xr + (size_t)d1 * 256 + cg);
                    float z0 = acc[mt][nt][2] + lv.x + rv.x;
                    float z1 = acc[mt][nt][3] + lv.y + rv.y;
                    z0 = z0 > 0.f ? z0 : 0.2f * z0;
                    z1 = z1 > 0.f ? z1 : 0.2f * z1;
                    p1 += a0 * z0 + a1 * z1;
                }
            }
            p0 += __shfl_xor_sync(0xffffffffu, p0, 1);
            p0 += __shfl_xor_sync(0xffffffffu, p0, 2);
            p1 += __shfl_xor_sync(0xffffffffu, p1, 1);
            p1 += __shfl_xor_sync(0xffffffffu, p1, 2);
            if ((lane & 3) == 0) {
                if (v0) {
                    C[(size_t)e0 * 4 + h] = p0;
                    atomicMax(mkey + (size_t)d0 * 4 + h, fkey(p0));
                }
                if (v1) {
                    C[(size_t)e1 * 4 + h] = p1;
                    atomicMax(mkey + (size_t)d1 * 4 + h, fkey(p1));
                }
            }
        }
    }
}

// ---------------- generic tiled fp32 GEMM (small cases) ---------------------
__global__ void gemm_bias(const float* __restrict__ A, const float* __restrict__ Bw,
                          const float* __restrict__ bias, float* __restrict__ C,
                          int M, int N, int K, float slope)
{
    __shared__ __align__(16) float As[16][128];
    __shared__ __align__(16) float Bs[16][64];
    int t  = threadIdx.x;
    int tx = t & 15;
    int ty = t >> 4;
    int rowBase = blockIdx.y * 128;
    int colBase = blockIdx.x * 64;

    float acc[8][4];
#pragma unroll
    for (int i = 0; i < 8; i++)
#pragma unroll
        for (int j = 0; j < 4; j++) acc[i][j] = 0.f;

    int nk = (K + 15) / 16;
    bool kvec = ((K & 15) == 0);
    for (int kt = 0; kt < nk; kt++) {
        int k0 = kt * 16;
        if (kvec) {
#pragma unroll
            for (int r = 0; r < 2; r++) {
                int i = t + r * 256;
                int m = i >> 2, kq = i & 3;
                int gm = rowBase + m;
                float4 v = make_float4(0.f, 0.f, 0.f, 0.f);
                if (gm < M) v = *(const float4*)(A + (long long)gm * K + k0 + kq * 4);
                As[kq*4+0][m] = v.x; As[kq*4+1][m] = v.y;
                As[kq*4+2][m] = v.z; As[kq*4+3][m] = v.w;
            }
        } else {
#pragma unroll
            for (int r = 0; r < 8; r++) {
                int i = t + r * 256;
                int m = i >> 4, kk = i & 15;
                int gm = rowBase + m, gk = k0 + kk;
                As[kk][m] = (gm < M && gk < K) ? A[(long long)gm * K + gk] : 0.f;
            }
        }
#pragma unroll
        for (int r = 0; r < 4; r++) {
            int i = t + r * 256;
            int kk = i >> 6, nn = i & 63;
            int gk = k0 + kk, gn = colBase + nn;
            Bs[kk][nn] = (gk < K && gn < N) ? Bw[(long long)gk * N + gn] : 0.f;
        }
        __syncthreads();
#pragma unroll
        for (int kk = 0; kk < 16; kk++) {
            float4 b4 = *(const float4*)&Bs[kk][tx * 4];
            float4 a0 = *(const float4*)&As[kk][ty * 8];
            float4 a1 = *(const float4*)&As[kk][ty * 8 + 4];
            float av[8] = {a0.x, a0.y, a0.z, a0.w, a1.x, a1.y, a1.z, a1.w};
            float bv[4] = {b4.x, b4.y, b4.z, b4.w};
#pragma unroll
            for (int i = 0; i < 8; i++)
#pragma unroll
                for (int j = 0; j < 4; j++) acc[i][j] += av[i] * bv[j];
        }
        __syncthreads();
    }
#pragma unroll
    for (int i = 0; i < 8; i++) {
        int gm = rowBase + ty * 8 + i;
        if (gm >= M) continue;
#pragma unroll
        for (int j = 0; j < 4; j++) {
            int gn = colBase + tx * 4 + j;
            if (gn >= N) continue;
            float v = acc[i][j] + bias[gn];
            if (slope >= 0.f) v = v > 0.f ? v : v * slope;
            C[(long long)gm * N + gn] = v;
        }
    }
}

// ---------------- prep / split kernels --------------------------------------
__global__ void init_keys(unsigned* __restrict__ k, int n) {
    int i = blockIdx.x * blockDim.x + threadIdx.x;
    if (i < n) k[i] = NEG_INF_KEY;
}
__global__ void transpose_pad_split(const float* __restrict__ in,
                                    __nv_bfloat16* __restrict__ oh,
                                    __nv_bfloat16* __restrict__ ol,
                                    int Kin, int Kout, int Ncols)
{
    int i = blockIdx.x * blockDim.x + threadIdx.x;
    if (i >= Ncols * Kout) return;
    int n = i / Kout, k = i % Kout;
    float v = (k < Kin) ? in[(size_t)k * Ncols + n] : 0.f;
    __nv_bfloat16 h = __float2bfloat16(v);
    oh[i] = h;
    ol[i] = __float2bfloat16(v - __bfloat162float(h));
}
__global__ void pad_ea_split(const float* __restrict__ ea,
                             __nv_bfloat16* __restrict__ oh,
                             __nv_bfloat16* __restrict__ ol, int E)
{
    int i = blockIdx.x * blockDim.x + threadIdx.x;
    if (i >= E * 64) return;
    int e = i >> 6, k = i & 63;
    float v = (k < 51) ? ea[(size_t)e * 51 + k] : 0.f;
    __nv_bfloat16 h = __float2bfloat16(v);
    oh[i] = h;
    ol[i] = __float2bfloat16(v - __bfloat162float(h));
}
__global__ void split_bf16(const float* __restrict__ src,
                           __nv_bfloat16* __restrict__ dh,
                           __nv_bfloat16* __restrict__ dl, int n)
{
    int i = blockIdx.x * blockDim.x + threadIdx.x;
    if (i >= n) return;
    float v = src[i];
    __nv_bfloat16 h = __float2bfloat16(v);
    dh[i] = h;
    dl[i] = __float2bfloat16(v - __bfloat162float(h));
}

// ---------------- fused exp + aggregation (warp per edge) -------------------
__global__ void gat_aggregate(const float* __restrict__ xl,
                              const int* __restrict__ ei,
                              const float* __restrict__ logit,
                              const unsigned* __restrict__ mkey,
                              float* __restrict__ den, float* __restrict__ agg, int E)
{
    int gw = (blockIdx.x * blockDim.x + threadIdx.x) >> 5;
    int lane = threadIdx.x & 31;
    if (gw >= E) return;
    long long e = gw;
    int s = ei[e], d = ei[(long long)E + e];
    int hA = lane >> 4, hB = 2 + hA;
    float wA = expf(logit[e * 4 + hA] - funkey(mkey[(size_t)d * 4 + hA]));
    float wB = expf(logit[e * 4 + hB] - funkey(mkey[(size_t)d * 4 + hB]));
    if ((lane & 15) == 0) {
        atomicAdd(&den[(size_t)d * 4 + hA], wA);
        atomicAdd(&den[(size_t)d * 4 + hB], wB);
    }
    int cA = lane * 4, cB = 128 + lane * 4;
    float4 xA = *(const float4*)(xl + (size_t)s * 256 + cA);
    float4 xB = *(const float4*)(xl + (size_t)s * 256 + cB);
    float* dp = agg + (size_t)d * 256;
    atomicAdd(dp + cA + 0, xA.x * wA);
    atomicAdd(dp + cA + 1, xA.y * wA);
    atomicAdd(dp + cA + 2, xA.z * wA);
    atomicAdd(dp + cA + 3, xA.w * wA);
    atomicAdd(dp + cB + 0, xB.x * wB);
    atomicAdd(dp + cB + 1, xB.y * wB);
    atomicAdd(dp + cB + 2, xB.z * wB);
    atomicAdd(dp + cB + 3, xB.w * wB);
}

// ---------------- normalize + bias + bf16 split ------------------------------
__global__ void finalize(const float* __restrict__ agg, const float* __restrict__ den,
                         const float* __restrict__ bias, float* __restrict__ out,
                         __nv_bfloat16* __restrict__ oh, __nv_bfloat16* __restrict__ ol,
                         int total)
{
    int i = blockIdx.x * blockDim.x + threadIdx.x;
    if (i >= total) return;
    int c = i & 255;
    int node = i >> 8;
    float v = agg[i] / (den[(size_t)node * 4 + (c >> 6)] + 1e-16f) + bias[c];
    out[i] = v;
    __nv_bfloat16 h = __float2bfloat16(v);
    oh[i] = h;
    ol[i] = __float2bfloat16(v - __bfloat162float(h));
}

// ---------------- pooling --------------------------------------------------
__global__ void pool_max(const float* __restrict__ a, const int* __restrict__ batch,
                         unsigned* __restrict__ keys, int total)
{
    int i = blockIdx.x * blockDim.x + threadIdx.x;
    if (i >= total) return;
    int b = batch[i >> 8];
    atomicMax(&keys[b * 256 + (i & 255)], fkey(a[i]));
}
__global__ void pool_fused(const float* __restrict__ a, const float* __restrict__ h,
                           const int* __restrict__ batch,
                           const unsigned* __restrict__ keys,
                           float* __restrict__ gsum, float* __restrict__ gvec, int total)
{
    int i = blockIdx.x * blockDim.x + threadIdx.x;
    if (i >= total) return;
    int b = batch[i >> 8];
    int c = i & 255;
    float aw = expf(a[i] - funkey(keys[b * 256 + c]));
    atomicAdd(&gsum[b * 256 + c], aw);
    atomicAdd(&gvec[b * 256 + c], h[i] * aw);
}
__global__ void pool_norm(float* __restrict__ gvec, const float* __restrict__ gsum, int n)
{
    int i = blockIdx.x * blockDim.x + threadIdx.x;
    if (i < n) gvec[i] = gvec[i] / (gsum[i] + 1e-16f);
}

// ---------------- batchnorm (train stats) + relu ---------------------------
__global__ void bn_relu(const float* __restrict__ y, const float* __restrict__ gamma,
                        const float* __restrict__ beta, float* __restrict__ yact)
{
    int c = threadIdx.x;
    float s = 0.f, s2 = 0.f;
    for (int m = 0; m < NB; m++) {
        float v = y[m * 256 + c];
        s += v; s2 += v * v;
    }
    float mu = s * (1.f / NB);
    float var = s2 * (1.f / NB) - mu * mu;
    float inv = rsqrtf(var + 1e-5f);
    float ga = gamma[c], be = beta[c];
    for (int m = 0; m < NB; m++) {
        float v = (y[m * 256 + c] - mu) * inv * ga + be;
        yact[m * 256 + c] = v > 0.f ? v : 0.f;
    }
}

// ---------------- launcher --------------------------------------------------
extern "C" void kernel_launch(void* const* d_in, const int* in_sizes, int n_in,
                              void* d_out, int out_size)
{
    const float* x     = (const float*)d_in[0];
    const int*   ei    = (const int*)d_in[1];
    const float* ea    = (const float*)d_in[2];
    const int*   batch = (const int*)d_in[3];
    const float* W0   = (const float*)d_in[4];  const float* b0   = (const float*)d_in[5];
    const float* Wl1  = (const float*)d_in[6];  const float* bl1  = (const float*)d_in[7];
    const float* Wr1  = (const float*)d_in[8];  const float* br1  = (const float*)d_in[9];
    const float* We1  = (const float*)d_in[10]; const float* att1 = (const float*)d_in[11];
    const float* bias1= (const float*)d_in[12];
    const float* Wl2  = (const float*)d_in[13]; const float* bl2  = (const float*)d_in[14];
    const float* Wr2  = (const float*)d_in[15]; const float* br2  = (const float*)d_in[16];
    const float* We2  = (const float*)d_in[17]; const float* att2 = (const float*)d_in[18];
    const float* bias2= (const float*)d_in[19];
    const float* Wp   = (const float*)d_in[20]; const float* bp   = (const float*)d_in[21];
    const float* Wo1  = (const float*)d_in[22]; const float* bo1  = (const float*)d_in[23];
    const float* gamma= (const float*)d_in[24]; const float* beta = (const float*)d_in[25];
    const float* Wo2  = (const float*)d_in[26]; const float* bo2  = (const float*)d_in[27];
    float* out = (float*)d_out;

    const int N = in_sizes[0] / 13;
    const int E = in_sizes[2] / 51;
    const int NOUT = in_sizes[26] / 256;   // 2001

    float *h0, *xl, *xr, *h1, *h2, *agg, *logit, *den, *a, *gsum, *gvec, *y, *yact;
    unsigned *mkey, *gmkey;
    __nv_bfloat16 *h0h, *h0l, *hh, *hl, *eah, *eal, *wth, *wtl;
    cudaGetSymbolAddress((void**)&h0,   g_h0);
    cudaGetSymbolAddress((void**)&xl,   g_xl);
    cudaGetSymbolAddress((void**)&xr,   g_xr);
    cudaGetSymbolAddress((void**)&h1,   g_h1);
    cudaGetSymbolAddress((void**)&h2,   g_h2);
    cudaGetSymbolAddress((void**)&agg,  g_agg);
    cudaGetSymbolAddress((void**)&logit,g_logit);
    cudaGetSymbolAddress((void**)&mkey, g_mkey);
    cudaGetSymbolAddress((void**)&den,  g_den);
    cudaGetSymbolAddress((void**)&a,    g_a);
    cudaGetSymbolAddress((void**)&gmkey,g_gmkey);
    cudaGetSymbolAddress((void**)&gsum, g_gsum);
    cudaGetSymbolAddress((void**)&gvec, g_gvec);
    cudaGetSymbolAddress((void**)&y,    g_y);
    cudaGetSymbolAddress((void**)&yact, g_yact);
    cudaGetSymbolAddress((void**)&h0h,  g_h0h);
    cudaGetSymbolAddress((void**)&h0l,  g_h0l);
    cudaGetSymbolAddress((void**)&hh,   g_hh);
    cudaGetSymbolAddress((void**)&hl,   g_hl);
    cudaGetSymbolAddress((void**)&eah,  g_eah);
    cudaGetSymbolAddress((void**)&eal,  g_eal);
    cudaGetSymbolAddress((void**)&wth,  g_wth);
    cudaGetSymbolAddress((void**)&wtl,  g_wtl);

    __nv_bfloat16* wL1h = wth + 0 * 65536; __nv_bfloat16* wL1l = wtl + 0 * 65536;
    __nv_bfloat16* wR1h = wth + 1 * 65536; __nv_bfloat16* wR1l = wtl + 1 * 65536;
    __nv_bfloat16* wL2h = wth + 2 * 65536; __nv_bfloat16* wL2l = wtl + 2 * 65536;
    __nv_bfloat16* wR2h = wth + 3 * 65536; __nv_bfloat16* wR2l = wtl + 3 * 65536;
    __nv_bfloat16* wPh  = wth + 4 * 65536; __nv_bfloat16* wPl  = wtl + 4 * 65536;
    __nv_bfloat16* wE1h = wth + 5 * 65536; __nv_bfloat16* wE1l = wtl + 5 * 65536;
    __nv_bfloat16* wE2h = wth + 6 * 65536; __nv_bfloat16* wE2l = wtl + 6 * 65536;

    cudaFuncSetAttribute(gemm_mma<0>, cudaFuncAttributeMaxDynamicSharedMemorySize, GEMM_SMEM);
    cudaFuncSetAttribute(gemm_mma<1>, cudaFuncAttributeMaxDynamicSharedMemorySize, GEMM_SMEM);

    const int Et = (E + 127) / 128;

    auto gemmF = [&](const float* A, const float* Bw, const float* bias, float* C,
                     int M, int Nc, int K, float slope) {
        dim3 grid((Nc + 63) / 64, (M + 127) / 128);
        gemm_bias<<<grid, 256>>>(A, Bw, bias, C, M, Nc, K, slope);
    };
    auto gemmT = [&](const __nv_bfloat16* Ahp, const __nv_bfloat16* Alp,
                     const __nv_bfloat16* Bhp, const __nv_bfloat16* Blp,
                     const float* bias, float* C, int M, int K) {
        gemm_mma<0><<<dim3(2, (M + 127) / 128), 256, GEMM_SMEM>>>(
            Ahp, Alp, Bhp, Blp, bias, C, M, K, nullptr, nullptr, nullptr, nullptr, 0);
    };

    // ---- prep: split-bf16 transposed weights + padded edge_attr ----
    transpose_pad_split<<<(256*128 + 255)/256, 256>>>(Wl1, wL1h, wL1l, 128, 128, 256);
    transpose_pad_split<<<(256*128 + 255)/256, 256>>>(Wr1, wR1h, wR1l, 128, 128, 256);
    transpose_pad_split<<<(256*256 + 255)/256, 256>>>(Wl2, wL2h, wL2l, 256, 256, 256);
    transpose_pad_split<<<(256*256 + 255)/256, 256>>>(Wr2, wR2h, wR2l, 256, 256, 256);
    transpose_pad_split<<<(256*256 + 255)/256, 256>>>(Wp,  wPh,  wPl,  256, 256, 256);
    transpose_pad_split<<<(256*64  + 255)/256, 256>>>(We1, wE1h, wE1l, 51, 64, 256);
    transpose_pad_split<<<(256*64  + 255)/256, 256>>>(We2, wE2h, wE2l, 51, 64, 256);
    pad_ea_split<<<(E*64 + 255)/256, 256>>>(ea, eah, eal, E);

    // init MLP: h0 = x @ W0 + b0 (K=13, fp32), then split
    gemmF(x, W0, b0, h0, N, 128, 13, -1.f);
    split_bf16<<<(N*128 + 255)/256, 256>>>(h0, h0h, h0l, N * 128);

    // ---- GAT layer 1 ----
    gemmT(h0h, h0l, wL1h, wL1l, bl1, xl, N, 128);
    gemmT(h0h, h0l, wR1h, wR1l, br1, xr, N, 128);
    cudaMemsetAsync(agg, 0, (size_t)N * 256 * sizeof(float));
    cudaMemsetAsync(den, 0, (size_t)N * 4 * sizeof(float));
    init_keys<<<(N * 4 + 255) / 256, 256>>>(mkey, N * 4);
    gemm_mma<1><<<dim3(2, Et), 256, GEMM_SMEM>>>(
        eah, eal, wE1h, wE1l, att1, logit, E, 64, xl, xr, ei, mkey, E);
    gat_aggregate<<<(E * 32 + 255) / 256, 256>>>(xl, ei, logit, mkey, den, agg, E);
    finalize<<<(N * 256 + 255) / 256, 256>>>(agg, den, bias1, h1, hh, hl, N * 256);

    // ---- GAT layer 2 ----
    gemmT(hh, hl, wL2h, wL2l, bl2, xl, N, 256);
    gemmT(hh, hl, wR2h, wR2l, br2, xr, N, 256);
    cudaMemsetAsync(agg, 0, (size_t)N * 256 * sizeof(float));
    cudaMemsetAsync(den, 0, (size_t)N * 4 * sizeof(float));
    init_keys<<<(N * 4 + 255) / 256, 256>>>(mkey, N * 4);
    gemm_mma<1><<<dim3(2, Et), 256, GEMM_SMEM>>>(
        eah, eal, wE2h, wE2l, att2, logit, E, 64, xl, xr, ei, mkey, E);
    gat_aggregate<<<(E * 32 + 255) / 256, 256>>>(xl, ei, logit, mkey, den, agg, E);
    finalize<<<(N * 256 + 255) / 256, 256>>>(agg, den, bias2, h2, hh, hl, N * 256);

    // ---- attention pooling ----
    gemmT(hh, hl, wPh, wPl, bp, a, N, 256);
    cudaMemsetAsync(gsum, 0, (size_t)NB * 256 * sizeof(float));
    cudaMemsetAsync(gvec, 0, (size_t)NB * 256 * sizeof(float));
    init_keys<<<(NB * 256 + 255) / 256, 256>>>(gmkey, NB * 256);
    pool_max  <<<(N * 256 + 255) / 256, 256>>>(a, batch, gmkey, N * 256);
    pool_fused<<<(N * 256 + 255) / 256, 256>>>(a, h2, batch, gmkey, gsum, gvec, N * 256);
    pool_norm <<<(NB * 256 + 255) / 256, 256>>>(gvec, gsum, NB * 256);

    // ---- output MLP (small, fp32) ----
    gemmF(gvec, Wo1, bo1, y, NB, 256, 256, -1.f);
    bn_relu<<<1, 256>>>(y, gamma, beta, yact);
    gemmF(yact, Wo2, bo2, out, NB, NOUT, 256, 0.01f);
}